// round 12
// baseline (speedup 1.0000x reference)
#include <cuda_runtime.h>
#include <math.h>

#define BB 4
#define NN 8192
#define NPOINT 409
#define GRES 28
#define NC 32768              // Morton space: 2^15
#define CAPR 32
#define CAPU 48
#define FT 1024
#define NBKT 256              // 32-point buckets
#define RBLK (BB*NN/FT)       // 32 repulsion blocks
// dynamic smem: pts4 + mind + bucket centers + bucket tmax + bucket argmax
#define SMEMSZ (NN*16 + NN*4 + NBKT*16 + NBKT*4 + NBKT*4)

__device__ int    g_counts[BB*NC];
__device__ int    g_cstart[BB*(NC+1)];
__device__ int    g_cursor[BB*NC];
__device__ int    g_ptcell[BB*NN];
__device__ int    g_sorted[BB*NN];     // sorted pos -> original index
__device__ float4 g_pts4[BB*NN];       // coords in Morton-sorted order
__device__ float  g_newxyz[BB*NPOINT*3];
__device__ float  g_rep_partial[RBLK];
__device__ float  g_uni_term[BB*NPOINT*5];

struct UniP { float thr[5], el[5], den[5], wgt[5]; int ns[5]; };

__device__ __forceinline__ int cc(float v) {
    int c = (int)floorf((v + 1.0f) * 14.0f);
    return min(max(c, 0), GRES - 1);
}
__device__ __forceinline__ unsigned mexp(unsigned v) {
    v &= 31u;
    v = (v | (v << 8)) & 0x100Fu;
    v = (v | (v << 4)) & 0x10C3u;
    v = (v | (v << 2)) & 0x9249u;
    return v;
}
__device__ __forceinline__ int mcell(int x, int y, int z) {
    return (int)(mexp(x) | (mexp(y) << 1) | (mexp(z) << 2));
}

__global__ void k_zero() {
    int i = blockIdx.x * blockDim.x + threadIdx.x;
    if (i < BB*NC) g_counts[i] = 0;
}

__global__ void k_count(const float* __restrict__ pcd) {
    int gid = blockIdx.x * blockDim.x + threadIdx.x;
    if (gid >= BB*NN) return;
    int b = gid >> 13, i = gid & (NN-1);
    const float* p = pcd + (size_t)b*NN*3 + (size_t)i*3;
    int c = mcell(cc(p[0]), cc(p[1]), cc(p[2]));
    g_ptcell[gid] = c;
    atomicAdd(&g_counts[b*NC + c], 1);
}

__global__ void k_scan() {
    int b = blockIdx.x, t = threadIdx.x;
    const int CPT = NC / 1024;           // 32
    int base = t * CPT, s = 0;
    for (int k = 0; k < CPT; k++) s += g_counts[b*NC + base + k];
    __shared__ int sh[1024];
    sh[t] = s; __syncthreads();
    for (int off = 1; off < 1024; off <<= 1) {
        int v = (t >= off) ? sh[t - off] : 0;
        __syncthreads(); sh[t] += v; __syncthreads();
    }
    int run = sh[t] - s;
    for (int k = 0; k < CPT; k++) {
        int c = base + k;
        g_cstart[b*(NC+1) + c] = run;
        g_cursor[b*NC + c] = run;
        run += g_counts[b*NC + c];
    }
    if (t == 0) g_cstart[b*(NC+1) + NC] = NN;
}

__global__ void k_scatter(const float* __restrict__ pcd) {
    int gid = blockIdx.x * blockDim.x + threadIdx.x;
    if (gid >= BB*NN) return;
    int b = gid >> 13, i = gid & (NN-1);
    int pos = atomicAdd(&g_cursor[b*NC + g_ptcell[gid]], 1);
    g_sorted[b*NN + pos] = i;
    const float* p = pcd + (size_t)b*NN*3 + (size_t)i*3;
    g_pts4[b*NN + pos] = make_float4(p[0], p[1], p[2], 0.0f);
}

__device__ __forceinline__ void ins5(float v, float t5[5]) {
    if (v < t5[4]) {
        t5[4] = v; float x;
        if (t5[4] < t5[3]) { x=t5[3]; t5[3]=t5[4]; t5[4]=x;
        if (t5[3] < t5[2]) { x=t5[2]; t5[2]=t5[3]; t5[3]=x;
        if (t5[2] < t5[1]) { x=t5[1]; t5[1]=t5[2]; t5[2]=x;
        if (t5[1] < t5[0]) { x=t5[0]; t5[0]=t5[1]; t5[1]=x; } } } }
    }
}
__device__ __forceinline__ float wmaxf(float v) {
    #pragma unroll
    for (int off = 16; off; off >>= 1) v = fmaxf(v, __shfl_xor_sync(0xffffffffu, v, off));
    return v;
}
__device__ __forceinline__ float wminf(float v) {
    #pragma unroll
    for (int off = 16; off; off >>= 1) v = fminf(v, __shfl_xor_sync(0xffffffffu, v, off));
    return v;
}

__global__ void __launch_bounds__(FT) k_main(const float* __restrict__ pcd,
                                             float thr_rep, float h2) {
    extern __shared__ char smem_raw[];
    __shared__ float4 sSeed;
    __shared__ float sred[32];
    int blk = blockIdx.x, t = threadIdx.x, lane = t & 31, warp = t >> 5;

    if (blk < BB) {
        // ---- FPS: smem mind, 32-pt warp-owned buckets with exact skip ----
        float4*   s4    = (float4*)smem_raw;          // [NN]
        float*    smind = (float*)(s4 + NN);          // [NN]
        float4*   bc    = (float4*)(smind + NN);      // [NBKT] center.xyz, radius
        unsigned* sbv   = (unsigned*)(bc + NBKT);     // [NBKT] tmax bits
        int*      sbi   = (int*)(sbv + NBKT);         // [NBKT] argmax sorted pos

        const float4* G4 = g_pts4 + (size_t)blk*NN;
        for (int k = t; k < NN; k += FT) { s4[k] = G4[k]; smind[k] = 1e10f; }
        __syncthreads();

        // bucket geometry: warp w owns buckets [w*8, w*8+8)
        for (int k = 0; k < 8; k++) {
            int j = warp*8 + k, base = j*32;
            float4 p = s4[base + lane];
            float mnx=wminf(p.x), mxx=wmaxf(p.x);
            float mny=wminf(p.y), mxy=wmaxf(p.y);
            float mnz=wminf(p.z), mxz=wmaxf(p.z);
            float cx=(mnx+mxx)*0.5f, cy=(mny+mxy)*0.5f, cz=(mnz+mxz)*0.5f;
            float dx=p.x-cx, dy=p.y-cy, dz=p.z-cz;
            float r2 = wmaxf(dx*dx+dy*dy+dz*dz);
            if (lane == 0) {
                bc[j] = make_float4(cx, cy, cz, sqrtf(r2)*1.00002f);
                sbv[j] = __float_as_uint(1e10f);
                sbi[j] = base;
            }
        }
        const float* P = pcd + (size_t)blk*NN*3;
        float sx=__ldg(P), sy=__ldg(P+1), sz=__ldg(P+2);   // seed 0 = original idx 0
        if (t == 0) {
            float* o = &g_newxyz[blk*NPOINT*3];
            o[0]=sx; o[1]=sy; o[2]=sz;
        }
        __syncthreads();

        for (int it = 1; it < NPOINT; it++) {
            // Phase B: update active buckets (warp-uniform skip, exact)
            #pragma unroll
            for (int k = 0; k < 8; k++) {
                int j = warp*8 + k;
                float4 cb = bc[j];
                float dxc=cb.x-sx, dyc=cb.y-sy, dzc=cb.z-sz;
                float ddc = dxc*dxc + dyc*dyc + dzc*dzc;
                float bound = cb.w + sqrtf(__uint_as_float(sbv[j]));
                if (ddc < bound*bound*1.00002f) {
                    int pos = j*32 + lane;
                    float4 p = s4[pos];
                    float dx=p.x-sx, dy=p.y-sy, dz=p.z-sz;
                    float m2 = fminf(smind[pos], dx*dx+dy*dy+dz*dz);
                    smind[pos] = m2;
                    unsigned vb = __float_as_uint(m2);
                    unsigned wm = __reduce_max_sync(0xffffffffu, vb);
                    unsigned ci = (vb == wm) ? (unsigned)pos : 0xffffffffu;
                    unsigned wi = __reduce_min_sync(0xffffffffu, ci);
                    if (lane == 0) { sbv[j] = wm; sbi[j] = (int)wi; }
                }
            }
            __syncthreads();
            // Phase C: warp0 argmax over 256 buckets (max val, min sorted pos)
            if (warp == 0) {
                unsigned bv = sbv[lane*8]; int bi = sbi[lane*8];
                #pragma unroll
                for (int k = 1; k < 8; k++) {
                    unsigned v = sbv[lane*8 + k]; int i2 = sbi[lane*8 + k];
                    if (v > bv || (v == bv && i2 < bi)) { bv = v; bi = i2; }
                }
                unsigned wm = __reduce_max_sync(0xffffffffu, bv);
                unsigned ci = (bv == wm) ? (unsigned)bi : 0xffffffffu;
                unsigned wi = __reduce_min_sync(0xffffffffu, ci);
                if (lane == 0) {
                    float4 s = s4[wi];
                    sSeed = s;
                    float* o = &g_newxyz[(blk*NPOINT + it)*3];
                    o[0]=s.x; o[1]=s.y; o[2]=s.z;
                }
            }
            __syncthreads();
            sx = sSeed.x; sy = sSeed.y; sz = sSeed.z;
        }
    } else {
        // -------- repulsion: 1 thread / point --------
        int gid = (blk - BB)*FT + t;
        int b = gid >> 13, i = gid & (NN-1);
        const float*  P  = pcd + (size_t)b*NN*3;
        const float4* S4 = g_pts4 + (size_t)b*NN;
        float xi=P[i*3], yi=P[i*3+1], zi=P[i*3+2];
        int cx=cc(xi), cy=cc(yi), cz=cc(zi);
        int hidx[CAPR]; float hdd[CAPR]; int hn = 0;
        for (int oz=-1; oz<=1; oz++) { int z=cz+oz; if ((unsigned)z>=GRES) continue;
          unsigned ez = mexp(z) << 2;
        for (int oy=-1; oy<=1; oy++) { int y=cy+oy; if ((unsigned)y>=GRES) continue;
          unsigned ey = ez | (mexp(y) << 1);
        for (int ox=-1; ox<=1; ox++) { int x=cx+ox; if ((unsigned)x>=GRES) continue;
            int c = (int)(ey | mexp(x));
            int s0=g_cstart[b*(NC+1)+c], e0=g_cstart[b*(NC+1)+c+1];
            for (int q=s0; q<e0; q++) {
                float4 v = __ldg(&S4[q]);
                float dx=v.x-xi, dy=v.y-yi, dz=v.z-zi;
                float d=dx*dx+dy*dy+dz*dz;
                if (d<=thr_rep && hn<CAPR) { hidx[hn]=g_sorted[b*NN+q]; hdd[hn]=d; hn++; }
            }
        } } }
        for (int a=1; a<hn; a++) {
            int ki=hidx[a]; float kd=hdd[a]; int c2=a-1;
            while (c2>=0 && hidx[c2]>ki) { hidx[c2+1]=hidx[c2]; hdd[c2+1]=hdd[c2]; c2--; }
            hidx[c2+1]=ki; hdd[c2+1]=kd;
        }
        int cnt = hn < 20 ? hn : 20;
        float t5[5] = {1e30f,1e30f,1e30f,1e30f,1e30f};
        for (int a=0; a<cnt; a++) ins5(hdd[a], t5);
        float fd = hdd[0];
        for (int a=cnt; a<20; a++) ins5(fd, t5);
        float csum = 0.0f;
        #pragma unroll
        for (int a=1; a<5; a++) {
            float d5 = fmaxf(t5[a], 0.0f);
            csum += 0.07f - sqrtf(d5)*expf(-d5/h2);
        }
        float v = csum;
        #pragma unroll
        for (int off=16; off; off>>=1) v += __shfl_down_sync(0xffffffffu, v, off);
        if (lane==0) sred[warp]=v;
        __syncthreads();
        if (warp==0) {
            float u = sred[lane];
            #pragma unroll
            for (int off=16; off; off>>=1) u += __shfl_down_sync(0xffffffffu, u, off);
            if (lane==0) g_rep_partial[blk-BB]=u;
        }
    }
}

__global__ void k_uniform(const float* __restrict__ pcd, UniP up) {
    int q = blockIdx.x * blockDim.x + threadIdx.x;
    if (q >= BB*NPOINT) return;
    int b = q / NPOINT;
    const float4* S4 = g_pts4 + (size_t)b*NN;
    float qx=g_newxyz[q*3], qy=g_newxyz[q*3+1], qz=g_newxyz[q*3+2];
    int cx=cc(qx), cy=cc(qy), cz=cc(qz);
    int cidx[CAPU]; float cd[CAPU], cxr[CAPU], cyr[CAPU], czr[CAPU];
    int cn = 0;
    float thrmax = up.thr[4];
    for (int oz=-2; oz<=2; oz++) { int z=cz+oz; if ((unsigned)z>=GRES) continue;
      unsigned ez = mexp(z) << 2;
    for (int oy=-2; oy<=2; oy++) { int y=cy+oy; if ((unsigned)y>=GRES) continue;
      unsigned ey = ez | (mexp(y) << 1);
    for (int ox=-2; ox<=2; ox++) { int x=cx+ox; if ((unsigned)x>=GRES) continue;
        int c = (int)(ey | mexp(x));
        int s0=g_cstart[b*(NC+1)+c], e0=g_cstart[b*(NC+1)+c+1];
        for (int k=s0; k<e0; k++) {
            float4 v = __ldg(&S4[k]);
            float dx=v.x-qx, dy=v.y-qy, dz=v.z-qz;
            float d=dx*dx+dy*dy+dz*dz;
            if (d<=thrmax && cn<CAPU) {
                cidx[cn]=g_sorted[b*NN+k]; cd[cn]=d;
                cxr[cn]=v.x; cyr[cn]=v.y; czr[cn]=v.z; cn++;
            }
        }
    } } }
    for (int a=1; a<cn; a++) {
        int ki=cidx[a]; float kd=cd[a], kx=cxr[a], ky=cyr[a], kz=czr[a];
        int c2=a-1;
        while (c2>=0 && cidx[c2]>ki) {
            cidx[c2+1]=cidx[c2]; cd[c2+1]=cd[c2];
            cxr[c2+1]=cxr[c2]; cyr[c2+1]=cyr[c2]; czr[c2+1]=czr[c2]; c2--;
        }
        cidx[c2+1]=ki; cd[c2+1]=kd; cxr[c2+1]=kx; cyr[c2+1]=ky; czr[c2+1]=kz;
    }
    for (int pi=0; pi<5; pi++) {
        float thr = up.thr[pi];
        int ns = up.ns[pi];
        int gsel[CAPU]; int gc = 0;
        for (int a=0; a<cn && gc<ns; a++) if (cd[a] <= thr) gsel[gc++] = a;
        int pads = ns - gc;
        float el = up.el[pi], den = up.den[pi];
        float ssum = 0.0f;
        for (int ii=0; ii<gc; ii++) {
            float ud;
            if (pads > 0 && ii == 0) ud = 0.0f;
            else {
                ud = 1e30f;
                int ai = gsel[ii];
                float ax=cxr[ai], ay=cyr[ai], az=czr[ai];
                for (int jj=0; jj<gc; jj++) {
                    if (jj == ii) continue;
                    int aj = gsel[jj];
                    float dx=cxr[aj]-ax, dy=cyr[aj]-ay, dz=czr[aj]-az;
                    ud = fminf(ud, dx*dx+dy*dy+dz*dz);
                }
            }
            float v = sqrtf(fabsf(ud + 1e-8f));
            float tt = v - el;
            ssum += tt*tt/den;
        }
        if (pads > 0) {
            float v = sqrtf(1e-8f);
            float tt = v - el;
            ssum += (float)pads * (tt*tt/den);
        }
        g_uni_term[q*5 + pi] = ssum;
    }
}

__global__ void k_final(float* __restrict__ out, UniP up) {
    __shared__ float sh[256];
    int t = threadIdx.x;
    float uni = 0.0f;
    for (int pi=0; pi<5; pi++) {
        float lo = 0.0f;
        for (int q=t; q<BB*NPOINT; q+=256) lo += g_uni_term[q*5+pi];
        sh[t]=lo; __syncthreads();
        for (int off=128; off; off>>=1) { if (t<off) sh[t]+=sh[t+off]; __syncthreads(); }
        if (t==0) uni += (sh[0] / ((float)(BB*NPOINT) * (float)up.ns[pi])) * up.wgt[pi];
        __syncthreads();
    }
    if (t==0) out[0] = uni / 5.0f;
    sh[t] = (t < RBLK) ? g_rep_partial[t] : 0.0f;
    __syncthreads();
    for (int off=128; off; off>>=1) { if (t<off) sh[t]+=sh[t+off]; __syncthreads(); }
    if (t==0) out[1] = sh[0] / (float)(BB*NN*4);
}

extern "C" void kernel_launch(void* const* d_in, const int* in_sizes, int n_in,
                              void* d_out, int out_size) {
    const float* pcd = (const float*)d_in[0];
    float* out = (float*)d_out;
    UniP up;
    const double ps[5] = {0.004, 0.008, 0.01, 0.012, 0.016};
    for (int i=0; i<5; i++) {
        int ns = (int)(8192.0 * ps[i]);
        double r = sqrt(ps[i]);
        double da = M_PI * ps[i] / ns;
        double el = sqrt(2.0 * da / 1.732);
        up.thr[i] = (float)(r*r);
        up.el[i]  = (float)el;
        up.den[i] = (float)(el + 1e-8);
        up.wgt[i] = (float)((ps[i]*100.0)*(ps[i]*100.0));
        up.ns[i]  = ns;
    }
    cudaFuncSetAttribute(k_main, cudaFuncAttributeMaxDynamicSharedMemorySize, SMEMSZ);
    k_zero<<<(BB*NC+255)/256, 256>>>();
    k_count<<<(BB*NN+255)/256, 256>>>(pcd);
    k_scan<<<BB, 1024>>>();
    k_scatter<<<(BB*NN+255)/256, 256>>>(pcd);
    k_main<<<BB+RBLK, FT, SMEMSZ>>>(pcd, (float)(0.07*0.07), (float)(0.03*0.03));
    k_uniform<<<(BB*NPOINT+255)/256, 256>>>(pcd, up);
    k_final<<<1, 256>>>(out, up);
}

// round 16
// speedup vs baseline: 2.0754x; 2.0754x over previous
#include <cuda_runtime.h>
#include <math.h>

#define BB 4
#define NN 8192
#define NPOINT 409
#define GRES 28
#define NC (GRES*GRES*GRES)
#define CAPR 32
#define CAPU 48

__device__ int    g_counts[BB*NC];
__device__ int    g_cstart[BB*(NC+1)];
__device__ int    g_cursor[BB*NC];
__device__ int    g_ptcell[BB*NN];
__device__ int    g_sorted[BB*NN];     // sorted pos -> original index
__device__ float4 g_pts4[BB*NN];       // coords in cell-sorted order
__device__ float  g_newxyz[BB*NPOINT*3];
__device__ float  g_rep_partial[32];
__device__ float  g_uni_term[BB*NPOINT*5];

struct UniP { float thr[5], el[5], den[5], wgt[5]; int ns[5]; };

// ---- f32x2 packed helpers (sm_103a) ----
#define PK2(out, lo, hi) \
    asm("mov.b64 %0, {%1, %2};" : "=l"(out) : "r"(lo), "r"(hi))
#define UPK2(lo, hi, in) \
    asm("mov.b64 {%0, %1}, %2;" : "=r"(lo), "=r"(hi) : "l"(in))
#define ADD2(out, a, b) \
    asm("add.rn.f32x2 %0, %1, %2;" : "=l"(out) : "l"(a), "l"(b))
#define MUL2(out, a, b) \
    asm("mul.rn.f32x2 %0, %1, %2;" : "=l"(out) : "l"(a), "l"(b))
#define FMA2(out, a, b, c) \
    asm("fma.rn.f32x2 %0, %1, %2, %3;" : "=l"(out) : "l"(a), "l"(b), "l"(c))

__device__ __forceinline__ int cc(float v) {
    int c = (int)floorf((v + 1.0f) * 14.0f);
    return min(max(c, 0), GRES - 1);
}

__global__ void k_zero() {
    int i = blockIdx.x * blockDim.x + threadIdx.x;
    if (i < BB*NC) g_counts[i] = 0;
}

__global__ void k_count(const float* __restrict__ pcd) {
    int gid = blockIdx.x * blockDim.x + threadIdx.x;
    if (gid >= BB*NN) return;
    int b = gid >> 13, i = gid & (NN-1);
    const float* p = pcd + (size_t)b*NN*3 + (size_t)i*3;
    int c = (cc(p[2])*GRES + cc(p[1]))*GRES + cc(p[0]);
    g_ptcell[gid] = c;
    atomicAdd(&g_counts[b*NC + c], 1);
}

__global__ void k_scan() {
    int b = blockIdx.x, t = threadIdx.x;
    const int CPT = (NC + 1023) / 1024;   // 22
    int base = t * CPT, s = 0;
    for (int k = 0; k < CPT; k++) { int c = base + k; if (c < NC) s += g_counts[b*NC + c]; }
    __shared__ int sh[1024];
    sh[t] = s; __syncthreads();
    for (int off = 1; off < 1024; off <<= 1) {
        int v = (t >= off) ? sh[t - off] : 0;
        __syncthreads(); sh[t] += v; __syncthreads();
    }
    int run = sh[t] - s;
    for (int k = 0; k < CPT; k++) {
        int c = base + k;
        if (c < NC) {
            g_cstart[b*(NC+1) + c] = run;
            g_cursor[b*NC + c] = run;
            run += g_counts[b*NC + c];
        }
    }
    if (t == 0) g_cstart[b*(NC+1) + NC] = NN;
}

__global__ void k_scatter(const float* __restrict__ pcd) {
    int gid = blockIdx.x * blockDim.x + threadIdx.x;
    if (gid >= BB*NN) return;
    int b = gid >> 13, i = gid & (NN-1);
    int pos = atomicAdd(&g_cursor[b*NC + g_ptcell[gid]], 1);
    g_sorted[b*NN + pos] = i;
    const float* p = pcd + (size_t)b*NN*3 + (size_t)i*3;
    g_pts4[b*NN + pos] = make_float4(p[0], p[1], p[2], 0.0f);
}

__device__ __forceinline__ void ins5(float v, float t5[5]) {
    if (v < t5[4]) {
        t5[4] = v; float x;
        if (t5[4] < t5[3]) { x=t5[3]; t5[3]=t5[4]; t5[4]=x;
        if (t5[3] < t5[2]) { x=t5[2]; t5[2]=t5[3]; t5[3]=x;
        if (t5[2] < t5[1]) { x=t5[1]; t5[1]=t5[2]; t5[2]=x;
        if (t5[1] < t5[0]) { x=t5[0]; t5[0]=t5[1]; t5[1]=x; } } } }
    }
}

__global__ void __launch_bounds__(1024) k_main(const float* __restrict__ pcd,
                                               float thr_rep, float h2) {
    extern __shared__ float4 s4[];       // [NN] points, FPS blocks only (128KB)
    __shared__ unsigned shV[2][32], shI[2][32];
    __shared__ float sred[32];
    int blk = blockIdx.x, t = threadIdx.x, lane = t & 31, warp = t >> 5;

    if (blk < BB) {
        // -------- FPS: register minds, f32x2 update, smem seed broadcast ----
        const float4* G4 = g_pts4 + (size_t)blk*NN;
        for (int k = t; k < NN; k += 1024) s4[k] = G4[k];
        __syncthreads();

        unsigned long long pxx[4], pyy[4], pzz[4];
        float mind[8];
        #pragma unroll
        for (int k = 0; k < 4; k++) {
            float4 a = s4[t*8 + 2*k], b = s4[t*8 + 2*k + 1];
            PK2(pxx[k], __float_as_uint(a.x), __float_as_uint(b.x));
            PK2(pyy[k], __float_as_uint(a.y), __float_as_uint(b.y));
            PK2(pzz[k], __float_as_uint(a.z), __float_as_uint(b.z));
            mind[2*k] = 1e10f; mind[2*k+1] = 1e10f;
        }
        const float* P = pcd + (size_t)blk*NN*3;
        float sx=__ldg(P), sy=__ldg(P+1), sz=__ldg(P+2);   // seed 0 = orig idx 0

        for (int it = 0; it < NPOINT; it++) {
            if (t == 0) {
                float* o = &g_newxyz[(blk*NPOINT + it)*3];
                o[0]=sx; o[1]=sy; o[2]=sz;
            }
            unsigned long long nsx2, nsy2, nsz2;
            unsigned nx = __float_as_uint(-sx), ny = __float_as_uint(-sy), nz = __float_as_uint(-sz);
            PK2(nsx2, nx, nx); PK2(nsy2, ny, ny); PK2(nsz2, nz, nz);
            float tmax = -1.0f;
            #pragma unroll
            for (int k = 0; k < 4; k++) {
                unsigned long long dx2, dy2, dz2, d2;
                ADD2(dx2, pxx[k], nsx2);
                ADD2(dy2, pyy[k], nsy2);
                ADD2(dz2, pzz[k], nsz2);
                MUL2(d2, dx2, dx2);
                FMA2(d2, dy2, dy2, d2);
                FMA2(d2, dz2, dz2, d2);
                unsigned ulo, uhi; UPK2(ulo, uhi, d2);
                mind[2*k]   = fminf(mind[2*k],   __uint_as_float(ulo));
                mind[2*k+1] = fminf(mind[2*k+1], __uint_as_float(uhi));
                tmax = fmaxf(tmax, fmaxf(mind[2*k], mind[2*k+1]));
            }
            unsigned vb = __float_as_uint(tmax);
            unsigned wm = __reduce_max_sync(0xffffffffu, vb);
            unsigned ci = 0xffffffffu;
            if (vb == wm) {
                #pragma unroll
                for (int k = 7; k >= 0; k--)          // descending -> lowest k wins
                    if (mind[k] == tmax) ci = (unsigned)(t*8 + k);
            }
            unsigned wi = __reduce_min_sync(0xffffffffu, ci);
            int buf = it & 1;
            if (lane == 0) { shV[buf][warp] = wm; shI[buf][warp] = wi; }
            __syncthreads();
            unsigned v2 = shV[buf][lane], i2 = shI[buf][lane];
            unsigned m2 = __reduce_max_sync(0xffffffffu, v2);
            unsigned c2 = (v2 == m2) ? i2 : 0xffffffffu;
            int sel = (int)__reduce_min_sync(0xffffffffu, c2);
            float4 s = s4[sel];                        // LDS broadcast (29cy)
            sx = s.x; sy = s.y; sz = s.z;
        }
    } else {
        // -------- repulsion: 1 thread / point --------
        int gid = (blk - BB)*1024 + t;
        int b = gid >> 13, i = gid & (NN-1);
        const float*  P  = pcd + (size_t)b*NN*3;
        const float4* S4 = g_pts4 + (size_t)b*NN;
        float xi=P[i*3], yi=P[i*3+1], zi=P[i*3+2];
        int cx=cc(xi), cy=cc(yi), cz=cc(zi);
        int hidx[CAPR]; float hdd[CAPR]; int hn = 0;
        for (int oz=-1; oz<=1; oz++) { int z=cz+oz; if ((unsigned)z>=GRES) continue;
        for (int oy=-1; oy<=1; oy++) { int y=cy+oy; if ((unsigned)y>=GRES) continue;
        for (int ox=-1; ox<=1; ox++) { int x=cx+ox; if ((unsigned)x>=GRES) continue;
            int c=(z*GRES+y)*GRES+x;
            int s0=g_cstart[b*(NC+1)+c], e0=g_cstart[b*(NC+1)+c+1];
            for (int q=s0; q<e0; q++) {
                float4 v = __ldg(&S4[q]);
                float dx=v.x-xi, dy=v.y-yi, dz=v.z-zi;
                float d=dx*dx+dy*dy+dz*dz;
                if (d<=thr_rep && hn<CAPR) { hidx[hn]=g_sorted[b*NN+q]; hdd[hn]=d; hn++; }
            }
        } } }
        for (int a=1; a<hn; a++) {
            int ki=hidx[a]; float kd=hdd[a]; int c2=a-1;
            while (c2>=0 && hidx[c2]>ki) { hidx[c2+1]=hidx[c2]; hdd[c2+1]=hdd[c2]; c2--; }
            hidx[c2+1]=ki; hdd[c2+1]=kd;
        }
        int cnt = hn < 20 ? hn : 20;
        float t5[5] = {1e30f,1e30f,1e30f,1e30f,1e30f};
        for (int a=0; a<cnt; a++) ins5(hdd[a], t5);
        float fd = hdd[0];
        for (int a=cnt; a<20; a++) ins5(fd, t5);
        float csum = 0.0f;
        #pragma unroll
        for (int a=1; a<5; a++) {
            float d5 = fmaxf(t5[a], 0.0f);
            csum += 0.07f - sqrtf(d5)*expf(-d5/h2);
        }
        float v = csum;
        #pragma unroll
        for (int off=16; off; off>>=1) v += __shfl_down_sync(0xffffffffu, v, off);
        if (lane==0) sred[warp]=v;
        __syncthreads();
        if (warp==0) {
            float u = sred[lane];
            #pragma unroll
            for (int off=16; off; off>>=1) u += __shfl_down_sync(0xffffffffu, u, off);
            if (lane==0) g_rep_partial[blk-BB]=u;
        }
    }
}

__global__ void k_uniform(const float* __restrict__ pcd, UniP up) {
    int q = blockIdx.x * blockDim.x + threadIdx.x;
    if (q >= BB*NPOINT) return;
    int b = q / NPOINT;
    const float4* S4 = g_pts4 + (size_t)b*NN;
    float qx=g_newxyz[q*3], qy=g_newxyz[q*3+1], qz=g_newxyz[q*3+2];
    int cx=cc(qx), cy=cc(qy), cz=cc(qz);
    int cidx[CAPU]; float cd[CAPU], cxr[CAPU], cyr[CAPU], czr[CAPU];
    int cn = 0;
    float thrmax = up.thr[4];
    for (int oz=-2; oz<=2; oz++) { int z=cz+oz; if ((unsigned)z>=GRES) continue;
    for (int oy=-2; oy<=2; oy++) { int y=cy+oy; if ((unsigned)y>=GRES) continue;
    for (int ox=-2; ox<=2; ox++) { int x=cx+ox; if ((unsigned)x>=GRES) continue;
        int c=(z*GRES+y)*GRES+x;
        int s0=g_cstart[b*(NC+1)+c], e0=g_cstart[b*(NC+1)+c+1];
        for (int k=s0; k<e0; k++) {
            float4 v = __ldg(&S4[k]);
            float dx=v.x-qx, dy=v.y-qy, dz=v.z-qz;
            float d=dx*dx+dy*dy+dz*dz;
            if (d<=thrmax && cn<CAPU) {
                cidx[cn]=g_sorted[b*NN+k]; cd[cn]=d;
                cxr[cn]=v.x; cyr[cn]=v.y; czr[cn]=v.z; cn++;
            }
        }
    } } }
    for (int a=1; a<cn; a++) {
        int ki=cidx[a]; float kd=cd[a], kx=cxr[a], ky=cyr[a], kz=czr[a];
        int c2=a-1;
        while (c2>=0 && cidx[c2]>ki) {
            cidx[c2+1]=cidx[c2]; cd[c2+1]=cd[c2];
            cxr[c2+1]=cxr[c2]; cyr[c2+1]=cyr[c2]; czr[c2+1]=czr[c2]; c2--;
        }
        cidx[c2+1]=ki; cd[c2+1]=kd; cxr[c2+1]=kx; cyr[c2+1]=ky; czr[c2+1]=kz;
    }
    for (int pi=0; pi<5; pi++) {
        float thr = up.thr[pi];
        int ns = up.ns[pi];
        int gsel[CAPU]; int gc = 0;
        for (int a=0; a<cn && gc<ns; a++) if (cd[a] <= thr) gsel[gc++] = a;
        int pads = ns - gc;
        float el = up.el[pi], den = up.den[pi];
        float ssum = 0.0f;
        for (int ii=0; ii<gc; ii++) {
            float ud;
            if (pads > 0 && ii == 0) ud = 0.0f;
            else {
                ud = 1e30f;
                int ai = gsel[ii];
                float ax=cxr[ai], ay=cyr[ai], az=czr[ai];
                for (int jj=0; jj<gc; jj++) {
                    if (jj == ii) continue;
                    int aj = gsel[jj];
                    float dx=cxr[aj]-ax, dy=cyr[aj]-ay, dz=czr[aj]-az;
                    ud = fminf(ud, dx*dx+dy*dy+dz*dz);
                }
            }
            float v = sqrtf(fabsf(ud + 1e-8f));
            float tt = v - el;
            ssum += tt*tt/den;
        }
        if (pads > 0) {
            float v = sqrtf(1e-8f);
            float tt = v - el;
            ssum += (float)pads * (tt*tt/den);
        }
        g_uni_term[q*5 + pi] = ssum;
    }
}

__global__ void k_final(float* __restrict__ out, UniP up) {
    __shared__ float sh[256];
    int t = threadIdx.x;
    float uni = 0.0f;
    for (int pi=0; pi<5; pi++) {
        float lo = 0.0f;
        for (int q=t; q<BB*NPOINT; q+=256) lo += g_uni_term[q*5+pi];
        sh[t]=lo; __syncthreads();
        for (int off=128; off; off>>=1) { if (t<off) sh[t]+=sh[t+off]; __syncthreads(); }
        if (t==0) uni += (sh[0] / ((float)(BB*NPOINT) * (float)up.ns[pi])) * up.wgt[pi];
        __syncthreads();
    }
    if (t==0) out[0] = uni / 5.0f;
    sh[t] = (t < 32) ? g_rep_partial[t] : 0.0f;
    __syncthreads();
    for (int off=128; off; off>>=1) { if (t<off) sh[t]+=sh[t+off]; __syncthreads(); }
    if (t==0) out[1] = sh[0] / (float)(BB*NN*4);
}

extern "C" void kernel_launch(void* const* d_in, const int* in_sizes, int n_in,
                              void* d_out, int out_size) {
    const float* pcd = (const float*)d_in[0];
    float* out = (float*)d_out;
    UniP up;
    const double ps[5] = {0.004, 0.008, 0.01, 0.012, 0.016};
    for (int i=0; i<5; i++) {
        int ns = (int)(8192.0 * ps[i]);
        double r = sqrt(ps[i]);
        double da = M_PI * ps[i] / ns;
        double el = sqrt(2.0 * da / 1.732);
        up.thr[i] = (float)(r*r);
        up.el[i]  = (float)el;
        up.den[i] = (float)(el + 1e-8);
        up.wgt[i] = (float)((ps[i]*100.0)*(ps[i]*100.0));
        up.ns[i]  = ns;
    }
    cudaFuncSetAttribute(k_main, cudaFuncAttributeMaxDynamicSharedMemorySize,
                         NN * (int)sizeof(float4));
    k_zero<<<(BB*NC+255)/256, 256>>>();
    k_count<<<(BB*NN+255)/256, 256>>>(pcd);
    k_scan<<<BB, 1024>>>();
    k_scatter<<<(BB*NN+255)/256, 256>>>(pcd);
    k_main<<<BB+32, 1024, NN*sizeof(float4)>>>(pcd, (float)(0.07*0.07), (float)(0.03*0.03));
    k_uniform<<<(BB*NPOINT+255)/256, 256>>>(pcd, up);
    k_final<<<1, 256>>>(out, up);
}